// round 4
// baseline (speedup 1.0000x reference)
#include <cuda_runtime.h>
#include <cstdint>

// out[dst] += x[src]. x: [N,64] f32, edge_index: [2,E] int32 on device.
// 16 threads per 4-edge group: each thread owns one float4 quad of FOUR
// consecutive edges (MLP=4 gather chains). Index loads vectorized as int4
// (E divisible by 4 in the benched shape; guarded tail otherwise).
// Gather via __ldg (x = 12.8MB, L2-resident), reduce via red.global.add.v4.f32.

__global__ void mp_zero_kernel(float4* __restrict__ out, int n4) {
    int i = blockIdx.x * blockDim.x + threadIdx.x;
    if (i < n4) out[i] = make_float4(0.f, 0.f, 0.f, 0.f);
}

__device__ __forceinline__ void red_add_v4(float* p, float4 v) {
    asm volatile("red.global.add.v4.f32 [%0], {%1, %2, %3, %4};"
                 :: "l"(p), "f"(v.x), "f"(v.y), "f"(v.z), "f"(v.w)
                 : "memory");
}

__global__ void mp_scatter_kernel(const float4* __restrict__ x,
                                  const int* __restrict__ ei,
                                  float* __restrict__ out,
                                  int E) {
    int idx = blockIdx.x * blockDim.x + threadIdx.x;
    int q  = idx & 15;          // quad within the 64-float row
    int g  = idx >> 4;          // 4-edge group id
    int e0 = g * 4;
    if (e0 >= E) return;

    if (e0 + 3 < E) {
        // Fast path: vector index loads (16B-aligned: e0 % 4 == 0).
        int4 s = __ldg((const int4*)(ei + e0));
        int4 d = __ldg((const int4*)(ei + E + e0));

        // 4 independent gathers in flight.
        float4 v0 = __ldg(x + s.x * 16 + q);
        float4 v1 = __ldg(x + s.y * 16 + q);
        float4 v2 = __ldg(x + s.z * 16 + q);
        float4 v3 = __ldg(x + s.w * 16 + q);

        red_add_v4(out + d.x * 64 + q * 4, v0);
        red_add_v4(out + d.y * 64 + q * 4, v1);
        red_add_v4(out + d.z * 64 + q * 4, v2);
        red_add_v4(out + d.w * 64 + q * 4, v3);
    } else {
        for (int e = e0; e < E; ++e) {
            int src = __ldg(ei + e);
            int dst = __ldg(ei + E + e);
            float4 v = __ldg(x + src * 16 + q);
            red_add_v4(out + dst * 64 + q * 4, v);
        }
    }
}

extern "C" void kernel_launch(void* const* d_in, const int* in_sizes, int n_in,
                              void* d_out, int out_size) {
    const float4* x = (const float4*)d_in[0];
    const int* ei = (const int*)d_in[1];
    float* out = (float*)d_out;

    int E = in_sizes[1] / 2;          // 800000
    int n4 = out_size / 4;

    {
        int threads = 256;
        int blocks = (n4 + threads - 1) / threads;
        mp_zero_kernel<<<blocks, threads>>>((float4*)out, n4);
    }
    {
        long long groups = (E + 3) / 4;
        long long work = groups * 16;
        int threads = 256;
        int blocks = (int)((work + threads - 1) / threads);
        mp_scatter_kernel<<<blocks, threads>>>(x, ei, out, E);
    }
}

// round 5
// speedup vs baseline: 1.2065x; 1.2065x over previous
#include <cuda_runtime.h>
#include <cstdint>

// out[dst] += x[src]. x: [N,64] f32, edge_index: [2,E] int32 on device.
//
// Two-phase: (1) bin edges by dst into fixed-capacity per-node lists in
// __device__ scratch (no scan needed), (2) node-parallel gather with register
// accumulation and ONE plain STG.128 per quad — eliminates the 12.8M
// red.global.v4 ops that bound the previous version (~35us of LTS atomic ALU).
// Overflow beyond CAP slots (prob ~1e-17 for this distribution) spills to a
// side buffer flushed with RED atomics after the main store — correct for any
// input. Falls back to the pure-atomic path if N exceeds the scratch size.

#define N_MAX  50000
#define CAP    64
#define MAX_OF 65536

__device__ int g_cnt[N_MAX];
__device__ int g_lists[N_MAX * CAP];
__device__ int g_of_src[MAX_OF];
__device__ int g_of_dst[MAX_OF];
__device__ int g_of_count;

__device__ __forceinline__ void red_add_v4(float* p, float4 v) {
    asm volatile("red.global.add.v4.f32 [%0], {%1, %2, %3, %4};"
                 :: "l"(p), "f"(v.x), "f"(v.y), "f"(v.z), "f"(v.w)
                 : "memory");
}

// ---- phase 0: reset counters --------------------------------------------
__global__ void mp_reset_kernel(int N) {
    int i = blockIdx.x * blockDim.x + threadIdx.x;
    if (i < N) g_cnt[i] = 0;
    if (i == 0) g_of_count = 0;
}

// ---- phase 1: bin edges by dst ------------------------------------------
__global__ void mp_fill_kernel(const int* __restrict__ ei, int E) {
    int e = blockIdx.x * blockDim.x + threadIdx.x;
    if (e >= E) return;
    int src = __ldg(ei + e);
    int dst = __ldg(ei + E + e);
    int p = atomicAdd(&g_cnt[dst], 1);
    if (p < CAP) {
        g_lists[dst * CAP + p] = src;
    } else {
        int o = atomicAdd(&g_of_count, 1);
        if (o < MAX_OF) { g_of_src[o] = src; g_of_dst[o] = dst; }
    }
}

// ---- phase 2: per-node gather-accumulate, plain store -------------------
__global__ void mp_gather_kernel(const float4* __restrict__ x,
                                 float4* __restrict__ out, int N) {
    int idx = blockIdx.x * blockDim.x + threadIdx.x;
    int node = idx >> 4;
    int q    = idx & 15;
    if (node >= N) return;

    int c = g_cnt[node];
    if (c > CAP) c = CAP;
    const int* lst = g_lists + node * CAP;

    float4 a0 = make_float4(0.f, 0.f, 0.f, 0.f);
    float4 a1 = make_float4(0.f, 0.f, 0.f, 0.f);
    int j = 0;
    for (; j + 1 < c; j += 2) {
        int s0 = __ldg(lst + j);
        int s1 = __ldg(lst + j + 1);
        float4 v0 = __ldg(x + s0 * 16 + q);
        float4 v1 = __ldg(x + s1 * 16 + q);
        a0.x += v0.x; a0.y += v0.y; a0.z += v0.z; a0.w += v0.w;
        a1.x += v1.x; a1.y += v1.y; a1.z += v1.z; a1.w += v1.w;
    }
    if (j < c) {
        int s0 = __ldg(lst + j);
        float4 v0 = __ldg(x + s0 * 16 + q);
        a0.x += v0.x; a0.y += v0.y; a0.z += v0.z; a0.w += v0.w;
    }
    a0.x += a1.x; a0.y += a1.y; a0.z += a1.z; a0.w += a1.w;
    out[node * 16 + q] = a0;
}

// ---- phase 3: flush overflow edges (expected none) ----------------------
__global__ void mp_overflow_kernel(const float4* __restrict__ x,
                                   float* __restrict__ out) {
    int n = g_of_count;
    if (n > MAX_OF) n = MAX_OF;
    for (int i = threadIdx.x; i < n * 16; i += blockDim.x) {
        int e = i >> 4, q = i & 15;
        int src = g_of_src[e];
        int dst = g_of_dst[e];
        float4 v = __ldg(x + src * 16 + q);
        red_add_v4(out + dst * 64 + q * 4, v);
    }
}

// ---- fallback (N > N_MAX): original atomic path -------------------------
__global__ void mp_zero_kernel(float4* __restrict__ out, int n4) {
    int i = blockIdx.x * blockDim.x + threadIdx.x;
    if (i < n4) out[i] = make_float4(0.f, 0.f, 0.f, 0.f);
}

__global__ void mp_scatter_kernel(const float4* __restrict__ x,
                                  const int* __restrict__ ei,
                                  float* __restrict__ out, int E) {
    int idx = blockIdx.x * blockDim.x + threadIdx.x;
    int e = idx >> 4, q = idx & 15;
    if (e >= E) return;
    int src = __ldg(ei + e);
    int dst = __ldg(ei + E + e);
    float4 v = __ldg(x + src * 16 + q);
    red_add_v4(out + dst * 64 + q * 4, v);
}

extern "C" void kernel_launch(void* const* d_in, const int* in_sizes, int n_in,
                              void* d_out, int out_size) {
    const float4* x = (const float4*)d_in[0];
    const int* ei = (const int*)d_in[1];
    float* out = (float*)d_out;

    int E = in_sizes[1] / 2;          // 800000
    int N = in_sizes[0] / 64;         // 50000

    if (N <= N_MAX) {
        mp_reset_kernel<<<(N + 255) / 256, 256>>>(N);
        mp_fill_kernel<<<(E + 255) / 256, 256>>>(ei, E);
        {
            long long work = (long long)N * 16;
            int blocks = (int)((work + 255) / 256);
            mp_gather_kernel<<<blocks, 256>>>(x, (float4*)out, N);
        }
        mp_overflow_kernel<<<1, 256>>>(x, out);
    } else {
        int n4 = out_size / 4;
        mp_zero_kernel<<<(n4 + 255) / 256, 256>>>((float4*)out, n4);
        long long work = (long long)E * 16;
        mp_scatter_kernel<<<(int)((work + 255) / 256), 256>>>(x, ei, out, E);
    }
}

// round 6
// speedup vs baseline: 1.2201x; 1.0113x over previous
#include <cuda_runtime.h>
#include <cstdint>

// out[dst] += x[src]. x: [N,64] f32, edge_index: [2,E] int32 on device.
//
// Two-phase: (1) bin edges by dst into fixed-capacity per-node lists in
// __device__ scratch, (2) node-parallel gather with register accumulation and
// one plain STG.128 per quad (no float atomics in the common path).
// Overflow beyond CAP slots (prob ~1e-17 for Binomial(800k,1/50k)) goes to a
// side buffer that the GATHER kernel folds into its accumulator before the
// store — no separate flush launch. Fallback atomic path for N > N_MAX.

#define N_MAX  50000
#define CAP    64
#define MAX_OF 65536

__device__ int g_cnt[N_MAX];
__device__ int g_lists[N_MAX * CAP];
__device__ int g_of_src[MAX_OF];
__device__ int g_of_dst[MAX_OF];
__device__ int g_of_count;

__device__ __forceinline__ void red_add_v4(float* p, float4 v) {
    asm volatile("red.global.add.v4.f32 [%0], {%1, %2, %3, %4};"
                 :: "l"(p), "f"(v.x), "f"(v.y), "f"(v.z), "f"(v.w)
                 : "memory");
}

__device__ __forceinline__ void acc_add(float4& a, float4 v) {
    a.x += v.x; a.y += v.y; a.z += v.z; a.w += v.w;
}

// ---- phase 0: reset counters --------------------------------------------
__global__ void mp_reset_kernel(int N) {
    int i = blockIdx.x * blockDim.x + threadIdx.x;
    if (i < N) g_cnt[i] = 0;
    if (i == 0) g_of_count = 0;
}

// ---- phase 1: bin edges by dst (4 edges per thread, int4 index loads) ----
__global__ void mp_fill_kernel(const int* __restrict__ ei, int E) {
    int g = blockIdx.x * blockDim.x + threadIdx.x;
    int e0 = g * 4;
    if (e0 >= E) return;

    int s[4], d[4];
    int m;
    if (e0 + 3 < E) {
        int4 sv = __ldg((const int4*)(ei + e0));
        int4 dv = __ldg((const int4*)(ei + E + e0));
        s[0] = sv.x; s[1] = sv.y; s[2] = sv.z; s[3] = sv.w;
        d[0] = dv.x; d[1] = dv.y; d[2] = dv.z; d[3] = dv.w;
        m = 4;
    } else {
        m = E - e0;
        for (int k = 0; k < m; ++k) {
            s[k] = __ldg(ei + e0 + k);
            d[k] = __ldg(ei + E + e0 + k);
        }
    }
    #pragma unroll
    for (int k = 0; k < 4; ++k) {
        if (k >= m) break;
        int p = atomicAdd(&g_cnt[d[k]], 1);
        if (p < CAP) {
            g_lists[d[k] * CAP + p] = s[k];
        } else {
            int o = atomicAdd(&g_of_count, 1);
            if (o < MAX_OF) { g_of_src[o] = s[k]; g_of_dst[o] = d[k]; }
        }
    }
}

// ---- phase 2: per-node gather-accumulate (+inline overflow), plain store --
__global__ void mp_gather_kernel(const float4* __restrict__ x,
                                 float4* __restrict__ out, int N) {
    int idx = blockIdx.x * blockDim.x + threadIdx.x;
    int node = idx >> 4;
    int q    = idx & 15;
    if (node >= N) return;

    int c = g_cnt[node];
    if (c > CAP) c = CAP;
    const int4* lst4 = (const int4*)(g_lists + node * CAP);

    float4 a0 = make_float4(0.f, 0.f, 0.f, 0.f);
    float4 a1 = make_float4(0.f, 0.f, 0.f, 0.f);
    float4 a2 = make_float4(0.f, 0.f, 0.f, 0.f);
    float4 a3 = make_float4(0.f, 0.f, 0.f, 0.f);

    int j = 0;
    for (; j + 3 < c; j += 4) {
        int4 s = __ldg(lst4 + (j >> 2));       // 4 src indices, one LDG
        float4 v0 = __ldg(x + s.x * 16 + q);   // 4 independent gather chains
        float4 v1 = __ldg(x + s.y * 16 + q);
        float4 v2 = __ldg(x + s.z * 16 + q);
        float4 v3 = __ldg(x + s.w * 16 + q);
        acc_add(a0, v0); acc_add(a1, v1); acc_add(a2, v2); acc_add(a3, v3);
    }
    if (j < c) {
        const int* lst = (const int*)lst4;
        for (; j < c; ++j) {
            int s0 = __ldg(lst + j);
            acc_add(a0, __ldg(x + s0 * 16 + q));
        }
    }

    // Fold in any overflow edges targeting this node (expected: none).
    int nof = g_of_count;
    if (nof > 0) {
        if (nof > MAX_OF) nof = MAX_OF;
        for (int i = 0; i < nof; ++i) {
            if (g_of_dst[i] == node)
                acc_add(a0, __ldg(x + g_of_src[i] * 16 + q));
        }
    }

    acc_add(a0, a1); acc_add(a2, a3); acc_add(a0, a2);
    out[node * 16 + q] = a0;
}

// ---- fallback (N > N_MAX): pure atomic path ------------------------------
__global__ void mp_zero_kernel(float4* __restrict__ out, int n4) {
    int i = blockIdx.x * blockDim.x + threadIdx.x;
    if (i < n4) out[i] = make_float4(0.f, 0.f, 0.f, 0.f);
}

__global__ void mp_scatter_kernel(const float4* __restrict__ x,
                                  const int* __restrict__ ei,
                                  float* __restrict__ out, int E) {
    int idx = blockIdx.x * blockDim.x + threadIdx.x;
    int e = idx >> 4, q = idx & 15;
    if (e >= E) return;
    int src = __ldg(ei + e);
    int dst = __ldg(ei + E + e);
    float4 v = __ldg(x + src * 16 + q);
    red_add_v4(out + dst * 64 + q * 4, v);
}

extern "C" void kernel_launch(void* const* d_in, const int* in_sizes, int n_in,
                              void* d_out, int out_size) {
    const float4* x = (const float4*)d_in[0];
    const int* ei = (const int*)d_in[1];
    float* out = (float*)d_out;

    int E = in_sizes[1] / 2;          // 800000
    int N = in_sizes[0] / 64;         // 50000

    if (N <= N_MAX) {
        mp_reset_kernel<<<(N + 255) / 256, 256>>>(N);
        {
            int groups = (E + 3) / 4;
            mp_fill_kernel<<<(groups + 255) / 256, 256>>>(ei, E);
        }
        {
            long long work = (long long)N * 16;
            mp_gather_kernel<<<(int)((work + 255) / 256), 256>>>(x, (float4*)out, N);
        }
    } else {
        int n4 = out_size / 4;
        mp_zero_kernel<<<(n4 + 255) / 256, 256>>>((float4*)out, n4);
        long long work = (long long)E * 16;
        mp_scatter_kernel<<<(int)((work + 255) / 256), 256>>>(x, ei, out, E);
    }
}